// round 2
// baseline (speedup 1.0000x reference)
#include <cuda_runtime.h>
#include <cuda_bf16.h>

// WaveletLinear: y[b,o] = sum_i w[o,i] * (1 - s^2) * exp(-0.5 s^2),
//   s = (x[b,i] - t[o,i]) / (A_MIN + softplus(scale_raw[o,i]) + EPS)
// B=512, O=1024, I=512.
//
// Math refactor:  c = sqrt(1/(2 ln2)),  s' = c*s,  u = s'^2  (>=0)
//   exp(-0.5 s^2) = ex2(-u)                    (neg folded into MUFU operand)
//   w*(1 - s^2)   = fma(-2ln2*w, u, w)         (positive u, no packed negate)
// Packed f32x2 FMAs (sm_103a FFMA2) keep the fma pipe below the MUFU floor.

#define I_DIM 512
#define RB 8   // batch rows per warp

typedef unsigned long long u64;

// Precomputed per-(o,i): c*inv, -c*t*inv, -2ln2*w   (6 MB static scratch)
__device__ float g_ivc[1024 * 512];
__device__ float g_tin[1024 * 512];
__device__ float g_w2n[1024 * 512];

__device__ __forceinline__ u64 fma2(u64 a, u64 b, u64 c) {
    u64 d; asm("fma.rn.f32x2 %0, %1, %2, %3;" : "=l"(d) : "l"(a), "l"(b), "l"(c)); return d;
}
__device__ __forceinline__ u64 mul2(u64 a, u64 b) {
    u64 d; asm("mul.rn.f32x2 %0, %1, %2;" : "=l"(d) : "l"(a), "l"(b)); return d;
}
// ex2(-a): neg.f32 folds into the MUFU source modifier in SASS
__device__ __forceinline__ float ex2neg(float a) {
    float r;
    asm("{ .reg .f32 t; neg.f32 t, %1; ex2.approx.ftz.f32 %0, t; }" : "=f"(r) : "f"(a));
    return r;
}
__device__ __forceinline__ u64 pack2(float lo, float hi) {
    u64 d; asm("mov.b64 %0, {%1, %2};" : "=l"(d) : "f"(lo), "f"(hi)); return d;
}
__device__ __forceinline__ float lo32(u64 v) { return __uint_as_float((unsigned)v); }
__device__ __forceinline__ float hi32(u64 v) { return __uint_as_float((unsigned)(v >> 32)); }

#define C_FOLD  0.84932180028801905f   // sqrt(1/(2 ln2))
#define TWO_LN2 1.38629436111989062f   // 2 ln2

__global__ void prep_kernel(const float* __restrict__ t,
                            const float* __restrict__ sraw,
                            const float* __restrict__ w,
                            int n)
{
    int idx = blockIdx.x * blockDim.x + threadIdx.x;
    if (idx < n) {
        float z  = sraw[idx];
        float sp = log1pf(__expf(z));
        float sc = 0.001f + sp + 1e-8f;
        float iv = 1.0f / sc;
        g_ivc[idx] = C_FOLD * iv;
        g_tin[idx] = -C_FOLD * t[idx] * iv;
        g_w2n[idx] = -TWO_LN2 * w[idx];
    }
}

__global__ __launch_bounds__(256)
void wavelet_kernel(const float* __restrict__ x,
                    const float* __restrict__ w,
                    float* __restrict__ out,
                    int O, int nbt /* B/RB */)
{
    const int warp = (blockIdx.x * 256 + threadIdx.x) >> 5;
    const int lane = threadIdx.x & 31;
    const int o  = warp >> 6;       // nbt = 64 => 8 warps (one block) share o
    const int bt = warp & 63;
    const int b0 = bt * RB;

    const ulonglong2* __restrict__ ivp = (const ulonglong2*)(g_ivc + (size_t)o * I_DIM);
    const ulonglong2* __restrict__ tnp = (const ulonglong2*)(g_tin + (size_t)o * I_DIM);
    const ulonglong2* __restrict__ w2p = (const ulonglong2*)(g_w2n + (size_t)o * I_DIM);
    const ulonglong2* __restrict__ wp  = (const ulonglong2*)(w     + (size_t)o * I_DIM);

    // two packed partial sums per batch row (pairs (x,y) and (z,w) of each float4)
    u64 acc0[RB], acc1[RB];
#pragma unroll
    for (int b = 0; b < RB; b++) { acc0[b] = 0ull; acc1[b] = 0ull; }

#pragma unroll
    for (int step = 0; step < I_DIM / 128; step++) {
        const int i4 = step * 32 + lane;   // 128-bit index: covers 128 i per step
        const ulonglong2 iv = ivp[i4];
        const ulonglong2 tn = tnp[i4];
        const ulonglong2 w2 = w2p[i4];
        const ulonglong2 wv = wp[i4];

#pragma unroll
        for (int b = 0; b < RB; b++) {
            const ulonglong2 xv =
                ((const ulonglong2*)(x + (size_t)(b0 + b) * I_DIM))[i4];

            // pair 0
            {
                u64 s  = fma2(xv.x, iv.x, tn.x);
                u64 u  = mul2(s, s);
                float e0 = ex2neg(lo32(u));
                float e1 = ex2neg(hi32(u));
                u64 ep = pack2(e0, e1);
                u64 pp = fma2(w2.x, u, wv.x);
                acc0[b] = fma2(pp, ep, acc0[b]);
            }
            // pair 1
            {
                u64 s  = fma2(xv.y, iv.y, tn.y);
                u64 u  = mul2(s, s);
                float e0 = ex2neg(lo32(u));
                float e1 = ex2neg(hi32(u));
                u64 ep = pack2(e0, e1);
                u64 pp = fma2(w2.y, u, wv.y);
                acc1[b] = fma2(pp, ep, acc1[b]);
            }
        }
    }

    // fold packed halves, then warp reduction over i-lanes
#pragma unroll
    for (int b = 0; b < RB; b++) {
        float a = lo32(acc0[b]) + hi32(acc0[b]) + lo32(acc1[b]) + hi32(acc1[b]);
#pragma unroll
        for (int off = 16; off > 0; off >>= 1)
            a += __shfl_xor_sync(0xFFFFFFFFu, a, off);
        if (lane == 0)
            out[(size_t)(b0 + b) * O + o] = a;
    }
}

extern "C" void kernel_launch(void* const* d_in, const int* in_sizes, int n_in,
                              void* d_out, int out_size)
{
    const float* x    = (const float*)d_in[0];  // (B, I)
    const float* t    = (const float*)d_in[1];  // (O, I)
    const float* sraw = (const float*)d_in[2];  // (O, I)
    const float* w    = (const float*)d_in[3];  // (O, I)
    float* out = (float*)d_out;                 // (B, O)

    const int OI = in_sizes[1];          // O * I
    const int BI = in_sizes[0];          // B * I
    const int O  = OI / I_DIM;           // 1024
    const int B  = BI / I_DIM;           // 512
    const int nbt = B / RB;              // 64

    prep_kernel<<<(OI + 255) / 256, 256>>>(t, sraw, w, OI);

    const int total_warps = O * nbt;
    wavelet_kernel<<<total_warps / 8, 256>>>(x, w, out, O, nbt);
}

// round 3
// speedup vs baseline: 1.2770x; 1.2770x over previous
#include <cuda_runtime.h>
#include <cuda_bf16.h>

// WaveletLinear: y[b,o] = sum_i w[o,i] * (1 - s^2) * exp(-0.5 s^2),
//   s = (x[b,i] - t[o,i]) / (A_MIN + softplus(scale_raw[o,i]) + EPS)
// B=512, O=1024, I=512.
//
// Math:  c^2 = 1/(2 ln2),  u = (c*s)^2  (>=0)
//   exp(-0.5 s^2) = ex2(-u)
//   w*(1 - s^2)   = fma(w2n, u, w),  w2n = -2ln2*w,  w = w2n * (-1/(2ln2))
// Packed f32x2 FMAs keep the fma pipe under the MUFU (EX2) floor.
// 3 precomputed streams: c*inv, -c*t*inv, -2ln2*w. w reconstructed per step.

#define I_DIM 512
#define RB 8   // batch rows per warp

typedef unsigned long long u64;

__device__ float g_ivc[1024 * 512];
__device__ float g_tin[1024 * 512];
__device__ float g_w2n[1024 * 512];

__device__ __forceinline__ u64 fma2(u64 a, u64 b, u64 c) {
    u64 d; asm("fma.rn.f32x2 %0, %1, %2, %3;" : "=l"(d) : "l"(a), "l"(b), "l"(c)); return d;
}
__device__ __forceinline__ u64 mul2(u64 a, u64 b) {
    u64 d; asm("mul.rn.f32x2 %0, %1, %2;" : "=l"(d) : "l"(a), "l"(b)); return d;
}
__device__ __forceinline__ float ex2neg(float a) {
    float r;
    asm("{ .reg .f32 t; neg.f32 t, %1; ex2.approx.ftz.f32 %0, t; }" : "=f"(r) : "f"(a));
    return r;
}
__device__ __forceinline__ u64 pack2(float lo, float hi) {
    u64 d; asm("mov.b64 %0, {%1, %2};" : "=l"(d) : "f"(lo), "f"(hi)); return d;
}
__device__ __forceinline__ float lo32(u64 v) { return __uint_as_float((unsigned)v); }
__device__ __forceinline__ float hi32(u64 v) { return __uint_as_float((unsigned)(v >> 32)); }

#define C_FOLD   0.84932180028801905f   // sqrt(1/(2 ln2))
#define TWO_LN2  1.38629436111989062f   // 2 ln2
#define NINV2LN2 (-0.72134752044448170f) // -1/(2 ln2)

__global__ void prep_kernel(const float* __restrict__ t,
                            const float* __restrict__ sraw,
                            const float* __restrict__ w,
                            int n)
{
    int idx = blockIdx.x * blockDim.x + threadIdx.x;
    if (idx < n) {
        float z  = sraw[idx];
        float sp = log1pf(__expf(z));
        float sc = 0.001f + sp + 1e-8f;
        float iv = 1.0f / sc;
        g_ivc[idx] = C_FOLD * iv;
        g_tin[idx] = -C_FOLD * t[idx] * iv;
        g_w2n[idx] = -TWO_LN2 * w[idx];
    }
}

__global__ __launch_bounds__(256, 3)
void wavelet_kernel(const float* __restrict__ x,
                    float* __restrict__ out,
                    int O)
{
    const int warp = (blockIdx.x * 256 + threadIdx.x) >> 5;
    const int lane = threadIdx.x & 31;
    const int o  = warp >> 6;       // 8 warps (one block) share o
    const int bt = warp & 63;
    const int b0 = bt * RB;

    const ulonglong2* __restrict__ ivp = (const ulonglong2*)(g_ivc + (size_t)o * I_DIM);
    const ulonglong2* __restrict__ tnp = (const ulonglong2*)(g_tin + (size_t)o * I_DIM);
    const ulonglong2* __restrict__ w2p = (const ulonglong2*)(g_w2n + (size_t)o * I_DIM);
    const ulonglong2* __restrict__ xp  = (const ulonglong2*)(x     + (size_t)b0 * I_DIM);

    const u64 KINV = pack2(NINV2LN2, NINV2LN2);

    u64 acc[RB];
#pragma unroll
    for (int b = 0; b < RB; b++) acc[b] = 0ull;

#pragma unroll
    for (int step = 0; step < I_DIM / 128; step++) {
        const int i4 = step * 32 + lane;   // 128-bit index: 128 i per step
        const ulonglong2 iv = ivp[i4];
        const ulonglong2 tn = tnp[i4];
        const ulonglong2 w2 = w2p[i4];
        // reconstruct w from w2n once per step (shared by all RB rows)
        const u64 wvx = mul2(w2.x, KINV);
        const u64 wvy = mul2(w2.y, KINV);

#pragma unroll
        for (int b = 0; b < RB; b++) {
            const ulonglong2 xv = xp[i4 + b * (I_DIM / 4)];

            // pair 0
            {
                u64 s  = fma2(xv.x, iv.x, tn.x);
                u64 u  = mul2(s, s);
                float e0 = ex2neg(lo32(u));
                float e1 = ex2neg(hi32(u));
                u64 ep = pack2(e0, e1);
                u64 pp = fma2(w2.x, u, wvx);
                acc[b] = fma2(pp, ep, acc[b]);
            }
            // pair 1
            {
                u64 s  = fma2(xv.y, iv.y, tn.y);
                u64 u  = mul2(s, s);
                float e0 = ex2neg(lo32(u));
                float e1 = ex2neg(hi32(u));
                u64 ep = pack2(e0, e1);
                u64 pp = fma2(w2.y, u, wvy);
                acc[b] = fma2(pp, ep, acc[b]);
            }
        }
    }

    // fold packed halves, then warp reduction over i-lanes
#pragma unroll
    for (int b = 0; b < RB; b++) {
        float a = lo32(acc[b]) + hi32(acc[b]);
#pragma unroll
        for (int off = 16; off > 0; off >>= 1)
            a += __shfl_xor_sync(0xFFFFFFFFu, a, off);
        if (lane == 0)
            out[(size_t)(b0 + b) * O + o] = a;
    }
}

extern "C" void kernel_launch(void* const* d_in, const int* in_sizes, int n_in,
                              void* d_out, int out_size)
{
    const float* x    = (const float*)d_in[0];  // (B, I)
    const float* t    = (const float*)d_in[1];  // (O, I)
    const float* sraw = (const float*)d_in[2];  // (O, I)
    const float* w    = (const float*)d_in[3];  // (O, I)
    float* out = (float*)d_out;                 // (B, O)

    const int OI = in_sizes[1];          // O * I
    const int BI = in_sizes[0];          // B * I
    const int O  = OI / I_DIM;           // 1024
    const int B  = BI / I_DIM;           // 512
    const int nbt = B / RB;              // 64

    prep_kernel<<<(OI + 255) / 256, 256>>>(t, sraw, w, OI);

    const int total_warps = O * nbt;
    wavelet_kernel<<<total_warps / 8, 256>>>(x, out, O);
}